// round 1
// baseline (speedup 1.0000x reference)
#include <cuda_runtime.h>
#include <math.h>

// Problem dims
#define B_  128
#define T_  256
#define C_  384
#define H_  6
#define D_  64
#define BT  (B_*T_)      // 32768 rows
#define FF  (4*C_)       // 1536
#define QKVW (3*C_)      // 1152

// ---------------- scratch (device globals; allocation-free) ----------------
__device__ float g_h1  [BT*C_];        // LN1 out
__device__ float g_qkv [BT*QKVW];      // q|k|v per row
__device__ float g_attn[BT*C_];        // attention out (concat heads)
__device__ float g_y1  [BT*C_];        // x + attn@Wp + bp
__device__ float g_h2  [BT*C_];        // LN2 out
__device__ float g_mid [BT*FF];        // relu(h2@W1+b1)
__device__ float g_Wqkv[C_*QKVW];      // repacked QKV weights [k][n]

// ---------------- LayerNorm: one block (128 thr) per row of 384 ----------------
__global__ void ln_kernel(const float* __restrict__ x, const float* __restrict__ g,
                          const float* __restrict__ beta, float* __restrict__ out)
{
    int row = blockIdx.x;
    const float* xr = x + (size_t)row * C_;
    int tid = threadIdx.x;

    float v0 = xr[tid], v1 = xr[tid + 128], v2 = xr[tid + 256];
    float s  = v0 + v1 + v2;
    float ss = v0*v0 + v1*v1 + v2*v2;

    #pragma unroll
    for (int o = 16; o > 0; o >>= 1) {
        s  += __shfl_xor_sync(0xffffffffu, s,  o);
        ss += __shfl_xor_sync(0xffffffffu, ss, o);
    }
    __shared__ float sh[8];
    int w = tid >> 5;
    if ((tid & 31) == 0) { sh[w*2] = s; sh[w*2+1] = ss; }
    __syncthreads();
    s  = sh[0] + sh[2] + sh[4] + sh[6];
    ss = sh[1] + sh[3] + sh[5] + sh[7];

    float mean = s * (1.0f / C_);
    float var  = ss * (1.0f / C_) - mean * mean;
    float rstd = rsqrtf(var + 1e-5f);

    float* orow = out + (size_t)row * C_;
    orow[tid      ] = (v0 - mean) * rstd * g[tid      ] + beta[tid      ];
    orow[tid + 128] = (v1 - mean) * rstd * g[tid + 128] + beta[tid + 128];
    orow[tid + 256] = (v2 - mean) * rstd * g[tid + 256] + beta[tid + 256];
}

// ---------------- repack Wq/Wk/Wv (H,C,Dh) -> Wqkv[k][n], n = which*384 + h*64 + d ----
__global__ void repack_kernel(const float* __restrict__ Wq, const float* __restrict__ Wk,
                              const float* __restrict__ Wv, float* __restrict__ Wqkv)
{
    int idx = blockIdx.x * blockDim.x + threadIdx.x;
    if (idx >= C_ * QKVW) return;
    int k = idx / QKVW;
    int n = idx % QKVW;
    int which = n / C_;
    int nn = n % C_;
    int h = nn / D_, d = nn % D_;
    const float* W = (which == 0) ? Wq : (which == 1) ? Wk : Wv;
    Wqkv[idx] = W[(size_t)h * C_ * D_ + (size_t)k * D_ + d];
}

// ---------------- tiled SGEMM: C = A[MxK] * B[KxN] (+bias)(+res)(+relu) ----------------
// BM=128 BN=64 BK=16, 256 threads, 8x4 per-thread microtile.
// EPI: 0 = plain, 1 = +bias, 2 = +bias+residual, 3 = +bias+relu
template<int EPI>
__global__ void sgemm_kernel(const float* __restrict__ A, const float* __restrict__ B,
                             const float* __restrict__ bias, const float* __restrict__ res,
                             float* __restrict__ C, int M, int N, int K)
{
    const int BM = 128, BN = 64, BK = 16;
    __shared__ float As[BK][BM + 1];   // transposed A tile, padded vs bank conflicts
    __shared__ float Bs[BK][BN];

    int tid = threadIdx.x;                 // 256
    int n0 = blockIdx.x * BN;
    int m0 = blockIdx.y * BM;
    int tx = tid & 15;                     // 16 col-groups (x4)
    int ty = tid >> 4;                     // 16 row-groups (x8)

    float acc[8][4];
    #pragma unroll
    for (int i = 0; i < 8; i++)
        #pragma unroll
        for (int j = 0; j < 4; j++) acc[i][j] = 0.f;

    for (int k0 = 0; k0 < K; k0 += BK) {
        // A tile: 128x16 = 2048 elems, 8 per thread (store transposed)
        #pragma unroll
        for (int i = 0; i < 8; i++) {
            int idx = tid + i * 256;
            int r = idx >> 4, c = idx & 15;
            As[c][r] = A[(size_t)(m0 + r) * K + k0 + c];
        }
        // B tile: 16x64 = 1024 elems, 4 per thread (coalesced)
        #pragma unroll
        for (int i = 0; i < 4; i++) {
            int idx = tid + i * 256;
            int r = idx >> 6, c = idx & 63;
            Bs[r][c] = B[(size_t)(k0 + r) * N + n0 + c];
        }
        __syncthreads();

        #pragma unroll
        for (int k = 0; k < BK; k++) {
            float a[8], bb[4];
            #pragma unroll
            for (int i = 0; i < 8; i++) a[i] = As[k][ty * 8 + i];
            #pragma unroll
            for (int j = 0; j < 4; j++) bb[j] = Bs[k][tx * 4 + j];
            #pragma unroll
            for (int i = 0; i < 8; i++)
                #pragma unroll
                for (int j = 0; j < 4; j++)
                    acc[i][j] += a[i] * bb[j];
        }
        __syncthreads();
    }

    #pragma unroll
    for (int i = 0; i < 8; i++) {
        int m = m0 + ty * 8 + i;
        #pragma unroll
        for (int j = 0; j < 4; j++) {
            int n = n0 + tx * 4 + j;
            float v = acc[i][j];
            if (EPI >= 1) v += bias[n];
            if (EPI == 2) v += res[(size_t)m * N + n];
            if (EPI == 3) v = fmaxf(v, 0.f);
            C[(size_t)m * N + n] = v;
        }
    }
}

// ---------------- fused causal attention: one block per (b,h), one query row per thread ----
__global__ void attn_kernel(const float* __restrict__ qkv, float* __restrict__ out)
{
    extern __shared__ float sm[];
    float* Ks = sm;              // [T_][D_]
    float* Vs = sm + T_ * D_;    // [T_][D_]

    int bh = blockIdx.x;
    int b = bh / H_, h = bh % H_;
    int tid = threadIdx.x;       // 256 = T_
    const float* base = qkv + (size_t)b * T_ * QKVW;

    // cooperative, coalesced load of K and V tiles for this (b,h)
    for (int idx = tid; idx < T_ * D_; idx += 256) {
        int s = idx >> 6, d = idx & 63;
        size_t roff = (size_t)s * QKVW + (size_t)h * D_;
        Ks[idx] = base[roff + C_   + d];
        Vs[idx] = base[roff + 2*C_ + d];
    }
    __syncthreads();

    const float scale = 0.05103103630798287f;   // 1/sqrt(384) (ref scales by n_embd)
    int t = tid;
    float q[D_];
    const float* qr = base + (size_t)t * QKVW + (size_t)h * D_;
    #pragma unroll
    for (int d = 0; d < D_; d++) q[d] = qr[d] * scale;

    float m = -1e30f, l = 0.f;
    float o[D_];
    #pragma unroll
    for (int d = 0; d < D_; d++) o[d] = 0.f;

    for (int s = 0; s <= t; s++) {      // s is warp-uniform -> smem broadcast
        const float* kr = Ks + s * D_;
        float x = 0.f;
        #pragma unroll
        for (int d = 0; d < D_; d++) x += q[d] * kr[d];
        float mn = fmaxf(m, x);
        float c  = __expf(m - mn);
        float p  = __expf(x - mn);
        l = l * c + p;
        const float* vr = Vs + s * D_;
        #pragma unroll
        for (int d = 0; d < D_; d++) o[d] = o[d] * c + p * vr[d];
        m = mn;
    }

    float inv = 1.f / l;
    float* orow = out + ((size_t)(b * T_ + t)) * C_ + (size_t)h * D_;
    #pragma unroll
    for (int d = 0; d < D_; d++) orow[d] = o[d] * inv;
}

// ---------------- launch ----------------
extern "C" void kernel_launch(void* const* d_in, const int* in_sizes, int n_in,
                              void* d_out, int out_size)
{
    const float* x   = (const float*)d_in[0];
    const float* Wq  = (const float*)d_in[1];
    const float* Wk  = (const float*)d_in[2];
    const float* Wv  = (const float*)d_in[3];
    const float* Wp  = (const float*)d_in[4];
    const float* bp  = (const float*)d_in[5];
    const float* W1  = (const float*)d_in[6];
    const float* b1  = (const float*)d_in[7];
    const float* W2  = (const float*)d_in[8];
    const float* b2  = (const float*)d_in[9];
    const float* g1  = (const float*)d_in[10];
    const float* be1 = (const float*)d_in[11];
    const float* g2  = (const float*)d_in[12];
    const float* be2 = (const float*)d_in[13];
    float* out = (float*)d_out;

    float *h1, *qkv, *attn, *y1, *h2, *mid, *Wqkv;
    cudaGetSymbolAddress((void**)&h1,   g_h1);
    cudaGetSymbolAddress((void**)&qkv,  g_qkv);
    cudaGetSymbolAddress((void**)&attn, g_attn);
    cudaGetSymbolAddress((void**)&y1,   g_y1);
    cudaGetSymbolAddress((void**)&h2,   g_h2);
    cudaGetSymbolAddress((void**)&mid,  g_mid);
    cudaGetSymbolAddress((void**)&Wqkv, g_Wqkv);

    // attention needs 128KB dynamic smem
    static const int ATTN_SMEM = 2 * T_ * D_ * (int)sizeof(float);
    cudaFuncSetAttribute(attn_kernel, cudaFuncAttributeMaxDynamicSharedMemorySize, ATTN_SMEM);

    // 1. LN1
    ln_kernel<<<BT, 128>>>(x, g1, be1, h1);

    // 2. repack QKV weights
    repack_kernel<<<(C_ * QKVW + 255) / 256, 256>>>(Wq, Wk, Wv, Wqkv);

    // 3. qkv = h1 @ Wqkv           [32768 x 1152]
    sgemm_kernel<0><<<dim3(QKVW / 64, BT / 128), 256>>>(h1, Wqkv, nullptr, nullptr, qkv, BT, QKVW, C_);

    // 4. fused causal attention    -> attn [32768 x 384]
    attn_kernel<<<B_ * H_, T_, ATTN_SMEM>>>(qkv, attn);

    // 5. y1 = x + attn @ Wp + bp
    sgemm_kernel<2><<<dim3(C_ / 64, BT / 128), 256>>>(attn, Wp, bp, x, y1, BT, C_, C_);

    // 6. LN2
    ln_kernel<<<BT, 128>>>(y1, g2, be2, h2);

    // 7. mid = relu(h2 @ W1 + b1)  [32768 x 1536]
    sgemm_kernel<3><<<dim3(FF / 64, BT / 128), 256>>>(h2, W1, b1, nullptr, mid, BT, FF, C_);

    // 8. out = y1 + mid @ W2 + b2  [32768 x 384]
    sgemm_kernel<2><<<dim3(C_ / 64, BT / 128), 256>>>(mid, W2, b2, y1, out, BT, C_, FF);
}

// round 3
// speedup vs baseline: 2.6145x; 2.6145x over previous
#include <cuda_runtime.h>
#include <math.h>
#include <stdint.h>

// Problem dims
#define B_  128
#define T_  256
#define C_  384
#define H_  6
#define D_  64
#define BT  (B_*T_)      // 32768 rows
#define FF  (4*C_)       // 1536
#define QKVW (3*C_)      // 1152

// ---------------- scratch (device globals; allocation-free) ----------------
__device__ float g_h1  [BT*C_];        // LN1 out
__device__ float g_qkv [BT*QKVW];      // q|k|v per row
__device__ float g_attn[BT*C_];        // attention out (concat heads)
__device__ float g_y1  [BT*C_];        // x + attn@Wp + bp
__device__ float g_h2  [BT*C_];        // LN2 out
__device__ float g_mid [BT*FF];        // relu(h2@W1+b1)
__device__ float g_Wqkv[C_*QKVW];      // repacked QKV weights [k][n]

// ---------------- LayerNorm: one block (128 thr) per row of 384 ----------------
__global__ void ln_kernel(const float* __restrict__ x, const float* __restrict__ g,
                          const float* __restrict__ beta, float* __restrict__ out)
{
    int row = blockIdx.x;
    const float* xr = x + (size_t)row * C_;
    int tid = threadIdx.x;

    float v0 = xr[tid], v1 = xr[tid + 128], v2 = xr[tid + 256];
    float s  = v0 + v1 + v2;
    float ss = v0*v0 + v1*v1 + v2*v2;

    #pragma unroll
    for (int o = 16; o > 0; o >>= 1) {
        s  += __shfl_xor_sync(0xffffffffu, s,  o);
        ss += __shfl_xor_sync(0xffffffffu, ss, o);
    }
    __shared__ float sh[8];
    int w = tid >> 5;
    if ((tid & 31) == 0) { sh[w*2] = s; sh[w*2+1] = ss; }
    __syncthreads();
    s  = sh[0] + sh[2] + sh[4] + sh[6];
    ss = sh[1] + sh[3] + sh[5] + sh[7];

    float mean = s * (1.0f / C_);
    float var  = ss * (1.0f / C_) - mean * mean;
    float rstd = rsqrtf(var + 1e-5f);

    float* orow = out + (size_t)row * C_;
    orow[tid      ] = (v0 - mean) * rstd * g[tid      ] + beta[tid      ];
    orow[tid + 128] = (v1 - mean) * rstd * g[tid + 128] + beta[tid + 128];
    orow[tid + 256] = (v2 - mean) * rstd * g[tid + 256] + beta[tid + 256];
}

// ---------------- repack Wq/Wk/Wv (H,C,Dh) -> Wqkv[k][n], n = which*384 + h*64 + d ----
__global__ void repack_kernel(const float* __restrict__ Wq, const float* __restrict__ Wk,
                              const float* __restrict__ Wv, float* __restrict__ Wqkv)
{
    int idx = blockIdx.x * blockDim.x + threadIdx.x;
    if (idx >= C_ * QKVW) return;
    int k = idx / QKVW;
    int n = idx % QKVW;
    int which = n / C_;
    int nn = n % C_;
    int h = nn / D_, d = nn % D_;
    const float* W = (which == 0) ? Wq : (which == 1) ? Wk : Wv;
    Wqkv[idx] = W[(size_t)h * C_ * D_ + (size_t)k * D_ + d];
}

// ---------------- helpers ----------------
__device__ __forceinline__ float to_tf32(float x) {
    uint32_t y;
    asm("cvt.rna.tf32.f32 %0, %1;" : "=r"(y) : "f"(x));
    return __uint_as_float(y);
}

__device__ __forceinline__ void ldsm_x4(uint32_t* r, uint32_t addr) {
    asm volatile("ldmatrix.sync.aligned.m8n8.x4.shared.b16 {%0,%1,%2,%3}, [%4];"
                 : "=r"(r[0]), "=r"(r[1]), "=r"(r[2]), "=r"(r[3]) : "r"(addr));
}

__device__ __forceinline__ void mma_tf32(float* c, const uint32_t* a, const uint32_t* b) {
    asm volatile("mma.sync.aligned.m16n8k8.row.col.f32.tf32.tf32.f32 "
                 "{%0,%1,%2,%3}, {%4,%5,%6,%7}, {%8,%9}, {%0,%1,%2,%3};"
                 : "+f"(c[0]), "+f"(c[1]), "+f"(c[2]), "+f"(c[3])
                 : "r"(a[0]), "r"(a[1]), "r"(a[2]), "r"(a[3]), "r"(b[0]), "r"(b[1]));
}

// ---------------- tf32 tensor-core GEMM: C = A[MxK]*B[KxN] (+bias)(+res)(+relu) ------
// BM=128 BN=128 BK=32. 256 threads = 8 warps (2 along M x 4 along N), warp tile 64x32.
// A frags via ldmatrix from padded As[m][36]; B frags via scalar LDS from Bs[k][132].
// EPI: 0 = plain, 2 = +bias+residual, 3 = +bias+relu
template<int EPI>
__global__ void __launch_bounds__(256, 2)
mma_gemm(const float* __restrict__ A, const float* __restrict__ B,
         const float* __restrict__ bias, const float* __restrict__ res,
         float* __restrict__ C, int M, int N, int K)
{
    const int BM = 128, BN = 128, BK = 32;
    const int APAD = BK + 4;   // 36 floats per A row
    const int BPAD = BN + 4;   // 132 floats per B row
    __shared__ float As[BM * APAD];
    __shared__ float Bs[BK * BPAD];

    int tid  = threadIdx.x;
    int warp = tid >> 5, lane = tid & 31;
    int wm = (warp >> 2) * 64;     // warp row offset (0/64)
    int wn = (warp & 3) * 32;      // warp col offset (0/32/64/96)
    int m0 = blockIdx.y * BM, n0 = blockIdx.x * BN;

    float acc[4][4][4];
    #pragma unroll
    for (int i = 0; i < 4; i++)
        #pragma unroll
        for (int j = 0; j < 4; j++)
            #pragma unroll
            for (int r = 0; r < 4; r++) acc[i][j][r] = 0.f;

    // ldmatrix lane addressing for A (x4: blocks = [r0-7,k0-3][r8-15,k0-3][r0-7,k4-7][r8-15,k4-7])
    int a_row  = lane & 15;
    int a_kofs = (lane & 16) ? 4 : 0;
    uint32_t As_base = (uint32_t)__cvta_generic_to_shared(As);
    uint32_t addrA[4];
    #pragma unroll
    for (int mt = 0; mt < 4; mt++)
        addrA[mt] = As_base + (((wm + mt * 16 + a_row) * APAD) + a_kofs) * 4u;

    int bl = lane & 3;    // k within frag
    int bc = lane >> 2;   // n within frag

    for (int k0 = 0; k0 < K; k0 += BK) {
        // stage A tile (128x32) as float4, rounding to tf32
        #pragma unroll
        for (int i = 0; i < 4; i++) {
            int idx = tid + i * 256;
            int r = idx >> 3, cg = idx & 7;
            float4 v = *(const float4*)(A + (size_t)(m0 + r) * K + k0 + cg * 4);
            float* d = As + r * APAD + cg * 4;
            d[0] = to_tf32(v.x); d[1] = to_tf32(v.y); d[2] = to_tf32(v.z); d[3] = to_tf32(v.w);
        }
        // stage B tile (32x128) as float4, rounding to tf32 (conflict-free)
        #pragma unroll
        for (int i = 0; i < 4; i++) {
            int idx = tid + i * 256;
            int r = idx >> 5, cg = idx & 31;
            float4 v = *(const float4*)(B + (size_t)(k0 + r) * N + n0 + cg * 4);
            float* d = Bs + r * BPAD + cg * 4;
            d[0] = to_tf32(v.x); d[1] = to_tf32(v.y); d[2] = to_tf32(v.z); d[3] = to_tf32(v.w);
        }
        __syncthreads();

        #pragma unroll
        for (int ks = 0; ks < 4; ks++) {
            uint32_t afr[4][4];
            #pragma unroll
            for (int mt = 0; mt < 4; mt++)
                ldsm_x4(afr[mt], addrA[mt] + ks * 32u);   // +8 floats per k-step

            uint32_t bfr[4][2];
            #pragma unroll
            for (int nt = 0; nt < 4; nt++) {
                int nn = wn + nt * 8 + bc;
                bfr[nt][0] = __float_as_uint(Bs[(ks * 8 + bl)     * BPAD + nn]);
                bfr[nt][1] = __float_as_uint(Bs[(ks * 8 + bl + 4) * BPAD + nn]);
            }
            #pragma unroll
            for (int mt = 0; mt < 4; mt++)
                #pragma unroll
                for (int nt = 0; nt < 4; nt++)
                    mma_tf32(acc[mt][nt], afr[mt], bfr[nt]);
        }
        __syncthreads();
    }

    // epilogue
    #pragma unroll
    for (int mt = 0; mt < 4; mt++) {
        int row = m0 + wm + mt * 16 + (lane >> 2);
        #pragma unroll
        for (int nt = 0; nt < 4; nt++) {
            int col = n0 + wn + nt * 8 + 2 * (lane & 3);
            float v0 = acc[mt][nt][0], v1 = acc[mt][nt][1];
            float v2 = acc[mt][nt][2], v3 = acc[mt][nt][3];
            if (EPI >= 1) {
                float b0 = bias[col], b1 = bias[col + 1];
                v0 += b0; v1 += b1; v2 += b0; v3 += b1;
            }
            if (EPI == 2) {
                float2 r0 = *(const float2*)(res + (size_t)row * N + col);
                float2 r1 = *(const float2*)(res + (size_t)(row + 8) * N + col);
                v0 += r0.x; v1 += r0.y; v2 += r1.x; v3 += r1.y;
            }
            if (EPI == 3) {
                v0 = fmaxf(v0, 0.f); v1 = fmaxf(v1, 0.f);
                v2 = fmaxf(v2, 0.f); v3 = fmaxf(v3, 0.f);
            }
            *(float2*)(C + (size_t)row * N + col)       = make_float2(v0, v1);
            *(float2*)(C + (size_t)(row + 8) * N + col) = make_float2(v2, v3);
        }
    }
}

// ---------------- fused causal attention ----------------
// grid = B*H*2 (half query ranges), 128 threads, one query row per thread.
// K/V streamed through smem in 128-row chunks (64KB) -> 3 CTAs/SM.
__global__ void attn_kernel(const float* __restrict__ qkv, float* __restrict__ out)
{
    extern __shared__ float sm[];
    float* Ks = sm;                 // [128][64]
    float* Vs = sm + 128 * D_;      // [128][64]

    int blk  = blockIdx.x;
    int half = blk & 1;
    int bh   = blk >> 1;
    int b = bh / H_, h = bh % H_;
    int tid = threadIdx.x;          // 128
    int t = half * 128 + tid;
    const float* base = qkv + (size_t)b * T_ * QKVW;

    const float scale = 0.05103103630798287f;   // 1/sqrt(384)
    float4 q4[16];
    const float4* qr = (const float4*)(base + (size_t)t * QKVW + (size_t)h * D_);
    #pragma unroll
    for (int i = 0; i < 16; i++) {
        float4 v = qr[i];
        q4[i] = make_float4(v.x * scale, v.y * scale, v.z * scale, v.w * scale);
    }

    float m = -1e30f, l = 0.f;
    float4 o4[16];
    #pragma unroll
    for (int i = 0; i < 16; i++) o4[i] = make_float4(0.f, 0.f, 0.f, 0.f);

    for (int c = 0; c <= half; c++) {
        int s0 = c * 128;
        if (c > 0) __syncthreads();
        // cooperative chunk load: 128 rows x 64 floats = 2048 float4
        for (int idx = tid; idx < 128 * 16; idx += 128) {
            int r = idx >> 4;
            size_t roff = (size_t)(s0 + r) * QKVW + (size_t)h * D_;
            ((float4*)Ks)[idx] = *(const float4*)(base + roff + C_ + (idx & 15) * 4);
            ((float4*)Vs)[idx] = *(const float4*)(base + roff + 2 * C_ + (idx & 15) * 4);
        }
        __syncthreads();

        int send = (t < s0 + 127) ? t : (s0 + 127);
        for (int s = s0; s <= send; s++) {
            const float4* kr = (const float4*)(Ks + (s - s0) * D_);
            float x = 0.f;
            #pragma unroll
            for (int i = 0; i < 16; i++) {
                float4 k = kr[i];
                x += q4[i].x * k.x + q4[i].y * k.y + q4[i].z * k.z + q4[i].w * k.w;
            }
            float mn = fmaxf(m, x);
            float cc = __expf(m - mn);
            float p  = __expf(x - mn);
            l = l * cc + p;
            const float4* vr = (const float4*)(Vs + (s - s0) * D_);
            #pragma unroll
            for (int i = 0; i < 16; i++) {
                float4 v = vr[i];
                o4[i].x = o4[i].x * cc + p * v.x;
                o4[i].y = o4[i].y * cc + p * v.y;
                o4[i].z = o4[i].z * cc + p * v.z;
                o4[i].w = o4[i].w * cc + p * v.w;
            }
            m = mn;
        }
    }

    float inv = 1.f / l;
    float4* orow = (float4*)(out + ((size_t)(b * T_ + t)) * C_ + (size_t)h * D_);
    #pragma unroll
    for (int i = 0; i < 16; i++)
        orow[i] = make_float4(o4[i].x * inv, o4[i].y * inv, o4[i].z * inv, o4[i].w * inv);
}

// ---------------- launch ----------------
extern "C" void kernel_launch(void* const* d_in, const int* in_sizes, int n_in,
                              void* d_out, int out_size)
{
    const float* x   = (const float*)d_in[0];
    const float* Wq  = (const float*)d_in[1];
    const float* Wk  = (const float*)d_in[2];
    const float* Wv  = (const float*)d_in[3];
    const float* Wp  = (const float*)d_in[4];
    const float* bp  = (const float*)d_in[5];
    const float* W1  = (const float*)d_in[6];
    const float* b1  = (const float*)d_in[7];
    const float* W2  = (const float*)d_in[8];
    const float* b2  = (const float*)d_in[9];
    const float* g1  = (const float*)d_in[10];
    const float* be1 = (const float*)d_in[11];
    const float* g2  = (const float*)d_in[12];
    const float* be2 = (const float*)d_in[13];
    float* out = (float*)d_out;

    float *h1, *qkv, *attn, *y1, *h2, *mid, *Wqkv;
    cudaGetSymbolAddress((void**)&h1,   g_h1);
    cudaGetSymbolAddress((void**)&qkv,  g_qkv);
    cudaGetSymbolAddress((void**)&attn, g_attn);
    cudaGetSymbolAddress((void**)&y1,   g_y1);
    cudaGetSymbolAddress((void**)&h2,   g_h2);
    cudaGetSymbolAddress((void**)&mid,  g_mid);
    cudaGetSymbolAddress((void**)&Wqkv, g_Wqkv);

    static const int ATTN_SMEM = 2 * 128 * D_ * (int)sizeof(float);   // 64KB
    cudaFuncSetAttribute(attn_kernel, cudaFuncAttributeMaxDynamicSharedMemorySize, ATTN_SMEM);

    // 1. LN1
    ln_kernel<<<BT, 128>>>(x, g1, be1, h1);

    // 2. repack QKV weights
    repack_kernel<<<(C_ * QKVW + 255) / 256, 256>>>(Wq, Wk, Wv, Wqkv);

    // 3. qkv = h1 @ Wqkv           [32768 x 1152]
    mma_gemm<0><<<dim3(QKVW / 128, BT / 128), 256>>>(h1, Wqkv, nullptr, nullptr, qkv, BT, QKVW, C_);

    // 4. fused causal attention    -> attn [32768 x 384]
    attn_kernel<<<B_ * H_ * 2, 128, ATTN_SMEM>>>(qkv, attn);

    // 5. y1 = x + attn @ Wp + bp
    mma_gemm<2><<<dim3(C_ / 128, BT / 128), 256>>>(attn, Wp, bp, x, y1, BT, C_, C_);

    // 6. LN2
    ln_kernel<<<BT, 128>>>(y1, g2, be2, h2);

    // 7. mid = relu(h2 @ W1 + b1)  [32768 x 1536]
    mma_gemm<3><<<dim3(FF / 128, BT / 128), 256>>>(h2, W1, b1, nullptr, mid, BT, FF, C_);

    // 8. out = y1 + mid @ W2 + b2  [32768 x 384]
    mma_gemm<2><<<dim3(C_ / 128, BT / 128), 256>>>(mid, W2, b2, y1, out, BT, C_, FF);
}